// round 15
// baseline (speedup 1.0000x reference)
#include <cuda_runtime.h>
#include <cuda_bf16.h>
#include <cstdint>

// ---------------------------------------------------------------------------
// SupConLossWithQueue:  Q=4096, bsz=256, B=4352, 2B=8704, D=128, T=0.07
// rows g in [3841,8193). log_prob = d/T - log(sum_{lab!=} exp(d/T)); row-max
// cancels; d/T<=14.3 so fp32 sum-exp needs no max tracking.
// R15 = 81.9us champion + (a) whole-quarter pk table staged once in prologue
// (per-tile pk traffic removed from steady loop), (b) two dummy launches to
// steer the ncu capture slot onto kgemm for diagnostics.
// ---------------------------------------------------------------------------
#define Qn      4096
#define BSZh    256
#define Bn      4352
#define N2      8704
#define Dk      128
#define ROW0    3841
#define NR      4352
#define NCLS    100
#define MAXP    512
#define NQ      4
#define COLQ    2176
#define NTILE   17
#define KRB     136
#define INV_T   14.2857142857142857f

__device__ __nv_bfloat16 g_cB[N2][Dk];
__device__ int           g_lab[N2];
__device__ int           g_pk[N2];          // (rank<<16)|label
__device__ int           g_cnt[NCLS];       // class sizes (zero-init .bss)
__device__ float         g_rowZ[NR][NQ];
__device__ float         g_posD[NR * MAXP]; // [row][rank]
__device__ float         g_blkSum[KRB];
__device__ unsigned int  g_ctr;             // zero-init .bss

// ---------------------------------------------------------------------------
__device__ __forceinline__ void mma16816(float* c, const uint32_t* a, uint32_t b0, uint32_t b1)
{
    asm volatile(
        "mma.sync.aligned.m16n8k16.row.col.f32.bf16.bf16.f32 "
        "{%0,%1,%2,%3}, {%4,%5,%6,%7}, {%8,%9}, {%0,%1,%2,%3};\n"
        : "+f"(c[0]), "+f"(c[1]), "+f"(c[2]), "+f"(c[3])
        : "r"(a[0]), "r"(a[1]), "r"(a[2]), "r"(a[3]), "r"(b0), "r"(b1));
}

__device__ __forceinline__ int lab_of(int c, const int* label, const int* lq)
{
    int i = (c >= Bn) ? c - Bn : c;
    return (i < BSZh) ? label[i] : ((i < Qn) ? lq[i] : label[i - Qn]);
}

// ---------------------------------------------------------------------------
// Dummy kernel: shifts the ncu capture slot so kgemm gets profiled.
// ---------------------------------------------------------------------------
__global__ void kdummy() {}

// ---------------------------------------------------------------------------
// Kernel P: gather contrast rows (bf16) + labels + fused rank assignment.
// 1088 blocks x 256 threads; 32 threads per column, 1 float4 each.
// ---------------------------------------------------------------------------
__global__ void __launch_bounds__(256) kprep(const float* __restrict__ feat,
                                             const int*   __restrict__ label,
                                             const float* __restrict__ fq,
                                             const float* __restrict__ fq2,
                                             const int*   __restrict__ lq)
{
    int gid = blockIdx.x * 256 + threadIdx.x;
    int c = gid >> 5, q = gid & 31;
    int half = (c >= Bn) ? 1 : 0;
    int i = c - half * Bn;

    const float* src;
    if (i < BSZh)      src = feat + (half ? i : (BSZh + i)) * Dk;
    else if (i < Qn)   src = (half ? fq2 : fq) + i * Dk;
    else               src = feat + ((half ? BSZh : 0) + (i - Qn)) * Dk;

    float4 v = *(const float4*)(src + q * 4);

    if (q == 0) {
        int l = lab_of(c, label, lq);
        g_lab[c] = l;
        int rank = atomicAdd(&g_cnt[l], 1);   // class-set invariant; order-free
        g_pk[c] = l | (rank << 16);
    }

    __nv_bfloat162 b01, b23;
    b01.x = __float2bfloat16(v.x); b01.y = __float2bfloat16(v.y);
    b23.x = __float2bfloat16(v.z); b23.y = __float2bfloat16(v.w);
    *(__nv_bfloat162*)(&g_cB[c][q * 4])     = b01;
    *(__nv_bfloat162*)(&g_cB[c][q * 4 + 2]) = b23;
}

// ---------------------------------------------------------------------------
// Kernel G: champion GEMM + whole-quarter pk table staged in prologue.
// bf16 MMA, M-tile 128 x N-quarter 2176, warp M16 x N128, K=128.
// Double-buffered B (1 sync/tile), LDG register prefetch.
// Dynamic smem 78.4 KB.  grid (34, 4) x 256 threads.
// ---------------------------------------------------------------------------
#define SMB0   0
#define SMB1   34816
#define SMPK   69632                     // 2176 ints = 8704 B
#define SMEM_BYTES 78336

__global__ void __launch_bounds__(256) kgemm()
{
    extern __shared__ __align__(16) unsigned char sm[];
    const uint32_t smem_base = (uint32_t)__cvta_generic_to_shared(sm);
    const int* sPk = (const int*)(sm + SMPK);

    const int tid  = threadIdx.x;
    const int lane = tid & 31;
    const int wid  = tid >> 5;          // warp owns rows wid*16 .. +15
    const int rowbase = blockIdx.x * 128;
    const int colbase = blockIdx.y * COLQ;

    // --- B prefetch regs: tile 0 ---
    const int br0 = tid >> 4, bch = tid & 15;
    uint4 breg[8];
#pragma unroll
    for (int j = 0; j < 8; j++)
        breg[j] = *(const uint4*)((const char*)g_cB[colbase + br0 + j * 16] + bch * 16);

    // --- stage pk table (whole quarter) + A into buf0 ---
    for (int i = tid; i < COLQ; i += 256)
        ((int*)(sm + SMPK))[i] = g_pk[colbase + i];
    for (int idx = tid; idx < 128 * 16; idx += 256) {
        int r = idx >> 4, ch = idx & 15;
        *(uint4*)(sm + SMB0 + r * 272 + ch * 16) =
            *(const uint4*)((const char*)g_cB[ROW0 + rowbase + r] + ch * 16);
    }
    __syncthreads();

    uint32_t afr[8][4];
    {
        uint32_t addr0 = smem_base + SMB0 + (wid * 16 + (lane & 15)) * 272 + ((lane >> 4) << 4);
#pragma unroll
        for (int ks = 0; ks < 8; ks++) {
            asm volatile("ldmatrix.sync.aligned.m8n8.x4.shared.b16 {%0,%1,%2,%3}, [%4];"
                         : "=r"(afr[ks][0]), "=r"(afr[ks][1]), "=r"(afr[ks][2]), "=r"(afr[ks][3])
                         : "r"(addr0 + ks * 32));
        }
    }
    __syncthreads();   // all A frags read; buf0 reusable for B

    // commit tile 0 into buf0; prefetch tile 1 into regs
#pragma unroll
    for (int j = 0; j < 8; j++)
        *(uint4*)(sm + SMB0 + (br0 + j * 16) * 272 + bch * 16) = breg[j];
#pragma unroll
    for (int j = 0; j < 8; j++)
        breg[j] = *(const uint4*)((const char*)g_cB[colbase + 128 + br0 + j * 16] + bch * 16);
    __syncthreads();   // buf0 visible to all

    const int w0 = rowbase + wid * 16 + (lane >> 2);
    const int w1 = w0 + 8;
    const int rl0 = g_lab[ROW0 + w0];
    const int rl1 = g_lab[ROW0 + w1];
    float z0 = 0.f, z1 = 0.f;

    const int bj = lane >> 3;
    const int bn_off = ((bj & 2) << 2) + (lane & 7);
    const uint32_t bk_off = (uint32_t)((bj & 1) << 4);

    for (int t = 0; t < NTILE; t++) {
        const uint32_t bufB  = (t & 1) ? SMB1 : SMB0;
        const uint32_t bufBn = (t & 1) ? SMB0 : SMB1;

        // commit tile t+1 into the OTHER buffer (its readers finished at t-1's sync)
        if (t + 1 < NTILE) {
#pragma unroll
            for (int j = 0; j < 8; j++)
                *(uint4*)(sm + bufBn + (br0 + j * 16) * 272 + bch * 16) = breg[j];
        }
        // prefetch tile t+2 (overlaps MMA below)
        if (t + 2 < NTILE) {
            int n0n = colbase + (t + 2) * 128;
#pragma unroll
            for (int j = 0; j < 8; j++)
                breg[j] = *(const uint4*)((const char*)g_cB[n0n + br0 + j * 16] + bch * 16);
        }

        // MMA: 16(M) x 128(N) per warp, K=128, reading buf[t&1]
        const uint32_t bbase = smem_base + bufB;
        float acc[16][4] = {};
#pragma unroll
        for (int ks = 0; ks < 8; ks++) {
#pragma unroll
            for (int gix = 0; gix < 8; gix++) {
                uint32_t ba = bbase + (uint32_t)((gix * 16 + bn_off) * 272)
                              + (uint32_t)(ks * 32) + bk_off;
                uint32_t b0, b1, b2, b3;
                asm volatile("ldmatrix.sync.aligned.m8n8.x4.shared.b16 {%0,%1,%2,%3}, [%4];"
                             : "=r"(b0), "=r"(b1), "=r"(b2), "=r"(b3) : "r"(ba));
                mma16816(acc[2 * gix],     afr[ks], b0, b1);
                mma16816(acc[2 * gix + 1], afr[ks], b2, b3);
            }
        }

        // epilogue: masked sum-of-exp + positive scatter (row-major)
        const int cb = t * 128 + 2 * (lane & 3);
#pragma unroll
        for (int f = 0; f < 16; f++) {
            int2 pk = *(const int2*)&sPk[cb + f * 8];
            int l0 = pk.x & 0xffff, l1 = pk.y & 0xffff;
            float x00 = acc[f][0] * INV_T, x01 = acc[f][1] * INV_T;
            float x10 = acc[f][2] * INV_T, x11 = acc[f][3] * INV_T;
            bool e00 = (l0 == rl0), e01 = (l1 == rl0);
            bool e10 = (l0 == rl1), e11 = (l1 == rl1);
            z0 += __expf(e00 ? -2e30f : x00) + __expf(e01 ? -2e30f : x01);
            z1 += __expf(e10 ? -2e30f : x10) + __expf(e11 ? -2e30f : x11);
            if (e00) g_posD[w0 * MAXP + (pk.x >> 16)] = x00;
            if (e01) g_posD[w0 * MAXP + (pk.y >> 16)] = x01;
            if (e10) g_posD[w1 * MAXP + (pk.x >> 16)] = x10;
            if (e11) g_posD[w1 * MAXP + (pk.y >> 16)] = x11;
        }
        __syncthreads();   // buf[(t+1)&1] committed; readers of buf[t&1] done
    }

    // reduce z across the 4 threads sharing each row
    z0 += __shfl_xor_sync(0xffffffffu, z0, 1);
    z0 += __shfl_xor_sync(0xffffffffu, z0, 2);
    z1 += __shfl_xor_sync(0xffffffffu, z1, 1);
    z1 += __shfl_xor_sync(0xffffffffu, z1, 2);
    if ((lane & 3) == 0) {
        g_rowZ[w0][blockIdx.y] = z0;
        g_rowZ[w1][blockIdx.y] = z1;
    }
}

// ---------------------------------------------------------------------------
// Kernel R: warp per row (136 blocks x 1024 thr), coalesced posD reads,
// fused final mean + counter reset for graph replay.
// ---------------------------------------------------------------------------
__global__ void __launch_bounds__(1024) krow(float* __restrict__ out)
{
    __shared__ float sW[32];
    __shared__ bool amLast;

    int tid = threadIdx.x, lane = tid & 31, wid = tid >> 5;
    int w = blockIdx.x * 32 + wid;
    int g = ROW0 + w;
    int rl = g_lab[g];
    bool exc = (g < Bn) || (g == 8192);
    int cnt = g_cnt[rl];
    int selfRank = g_pk[g] >> 16;

    float4 zz = *(const float4*)g_rowZ[w];
    float lse = __logf((zz.x + zz.y) + (zz.z + zz.w));

    float s = 0.f;
    for (int idx = lane; idx < cnt; idx += 32) {
        float x = g_posD[w * MAXP + idx];      // coalesced 128B per warp
        if (!(exc && idx == selfRank)) s += fminf(0.f, x - lse);
    }
    s += __shfl_xor_sync(0xffffffffu, s, 16);
    s += __shfl_xor_sync(0xffffffffu, s, 8);
    s += __shfl_xor_sync(0xffffffffu, s, 4);
    s += __shfl_xor_sync(0xffffffffu, s, 2);
    s += __shfl_xor_sync(0xffffffffu, s, 1);
    if (lane == 0) sW[wid] = s / (float)(cnt - (exc ? 1 : 0));
    __syncthreads();

    if (wid == 0) {
        float v = sW[lane];
        v += __shfl_xor_sync(0xffffffffu, v, 16);
        v += __shfl_xor_sync(0xffffffffu, v, 8);
        v += __shfl_xor_sync(0xffffffffu, v, 4);
        v += __shfl_xor_sync(0xffffffffu, v, 2);
        v += __shfl_xor_sync(0xffffffffu, v, 1);
        if (lane == 0) {
            g_blkSum[blockIdx.x] = v;
            __threadfence();
            amLast = (atomicAdd(&g_ctr, 1u) == gridDim.x - 1);
        }
    }
    __syncthreads();
    if (amLast) {
        // reset class counters for the next graph replay
        if (tid < NCLS) g_cnt[tid] = 0;
        if (tid == 0) {
            float a = 0.f;
#pragma unroll
            for (int i = 0; i < KRB; i++) a += g_blkSum[i];
            float loss = -(a / (float)NR);
            out[0] = loss; out[1] = loss; out[2] = loss;
            g_ctr = 0u;
        }
    }
}

// ---------------------------------------------------------------------------
extern "C" void kernel_launch(void* const* d_in, const int* in_sizes, int n_in,
                              void* d_out, int out_size)
{
    const float* feat  = (const float*)d_in[0];
    const int*   label = (const int*)d_in[1];
    const float* fq    = (const float*)d_in[2];
    const float* fq2   = (const float*)d_in[3];
    const int*   lq    = (const int*)d_in[4];
    float* out = (float*)d_out;

    cudaFuncSetAttribute(kgemm, cudaFuncAttributeMaxDynamicSharedMemorySize, SMEM_BYTES);

    kdummy<<<1, 1>>>();     // shift ncu capture slot
    kdummy<<<1, 1>>>();     // (targets kgemm as ~4th launch)
    kprep<<<(N2 * 32) / 256, 256>>>(feat, label, fq, fq2, lq);
    kgemm<<<dim3(NR / 128, NQ), 256, SMEM_BYTES>>>();
    krow<<<KRB, 1024>>>(out);
}

// round 17
// speedup vs baseline: 1.1830x; 1.1830x over previous
#include <cuda_runtime.h>
#include <cuda_bf16.h>
#include <cstdint>

// ---------------------------------------------------------------------------
// SupConLossWithQueue:  Q=4096, bsz=256, B=4352, 2B=8704, D=128, T=0.07
// rows g in [3841,8193). log_prob = d/T - log(sum_{lab!=} exp(d/T)); row-max
// cancels; d/T<=14.3 so fp32 sum-exp needs no max tracking.
// R16 (resubmit): occupancy fix. ncu showed kgemm latency-bound (occ 12.5%,
// tensor 23%, no pipe >40%). M-tile 64, acc 32 regs, cp.async 3-buffer ring
// (no breg), __launch_bounds__(256,2) -> 2 CTAs/SM (16 warps).
// ---------------------------------------------------------------------------
#define Qn      4096
#define BSZh    256
#define Bn      4352
#define N2      8704
#define Dk      128
#define ROW0    3841
#define NR      4352
#define NCLS    100
#define MAXP    512
#define NQ      4
#define COLQ    2176
#define NTILE   17
#define KRB     136
#define INV_T   14.2857142857142857f

__device__ __nv_bfloat16 g_cB[N2][Dk];
__device__ int           g_lab[N2];
__device__ int           g_pk[N2];          // (rank<<16)|label
__device__ int           g_cnt[NCLS];       // class sizes (zero-init .bss)
__device__ float         g_rowZ[NR][NQ];
__device__ float         g_posD[NR * MAXP]; // [row][rank]
__device__ float         g_blkSum[KRB];
__device__ unsigned int  g_ctr;             // zero-init .bss

// ---------------------------------------------------------------------------
__device__ __forceinline__ void mma16816(float* c, const uint32_t* a, uint32_t b0, uint32_t b1)
{
    asm volatile(
        "mma.sync.aligned.m16n8k16.row.col.f32.bf16.bf16.f32 "
        "{%0,%1,%2,%3}, {%4,%5,%6,%7}, {%8,%9}, {%0,%1,%2,%3};\n"
        : "+f"(c[0]), "+f"(c[1]), "+f"(c[2]), "+f"(c[3])
        : "r"(a[0]), "r"(a[1]), "r"(a[2]), "r"(a[3]), "r"(b0), "r"(b1));
}

__device__ __forceinline__ int lab_of(int c, const int* label, const int* lq)
{
    int i = (c >= Bn) ? c - Bn : c;
    return (i < BSZh) ? label[i] : ((i < Qn) ? lq[i] : label[i - Qn]);
}

// ---------------------------------------------------------------------------
// Kernel P: gather contrast rows (bf16) + labels + fused rank assignment.
// 1088 blocks x 256 threads; 32 threads per column, 1 float4 each.
// ---------------------------------------------------------------------------
__global__ void __launch_bounds__(256) kprep(const float* __restrict__ feat,
                                             const int*   __restrict__ label,
                                             const float* __restrict__ fq,
                                             const float* __restrict__ fq2,
                                             const int*   __restrict__ lq)
{
    int gid = blockIdx.x * 256 + threadIdx.x;
    int c = gid >> 5, q = gid & 31;
    int half = (c >= Bn) ? 1 : 0;
    int i = c - half * Bn;

    const float* src;
    if (i < BSZh)      src = feat + (half ? i : (BSZh + i)) * Dk;
    else if (i < Qn)   src = (half ? fq2 : fq) + i * Dk;
    else               src = feat + ((half ? BSZh : 0) + (i - Qn)) * Dk;

    float4 v = *(const float4*)(src + q * 4);

    if (q == 0) {
        int l = lab_of(c, label, lq);
        g_lab[c] = l;
        int rank = atomicAdd(&g_cnt[l], 1);   // class-set invariant; order-free
        g_pk[c] = l | (rank << 16);
    }

    __nv_bfloat162 b01, b23;
    b01.x = __float2bfloat16(v.x); b01.y = __float2bfloat16(v.y);
    b23.x = __float2bfloat16(v.z); b23.y = __float2bfloat16(v.w);
    *(__nv_bfloat162*)(&g_cB[c][q * 4])     = b01;
    *(__nv_bfloat162*)(&g_cB[c][q * 4 + 2]) = b23;
}

// ---------------------------------------------------------------------------
// Kernel G: M-tile 64 x N-quarter 2176, warp M16 x N64 (grid 4M x 2N).
// cp.async 3-buffer B ring (depth-2 pipeline), 1 sync/tile.
// grid (68, 4) x 256 threads, 2 CTAs/SM. Dynamic smem ~111 KB.
// ---------------------------------------------------------------------------
#define SMB0   0
#define SMB1   34816
#define SMB2   69632
#define SMPK   104448                    // 2176 ints = 8704 B
#define SMZ    113152                    // 128 floats = 512 B
#define SMEM_BYTES 113664

__device__ __forceinline__ void cp_tile(uint32_t dstbase, int srcrow, int tid)
{
#pragma unroll
    for (int i = 0; i < 8; i++) {
        int cid = tid + i * 256;
        int row = cid >> 4, ch = cid & 15;
        asm volatile("cp.async.cg.shared.global [%0], [%1], 16;\n"
                     :: "r"(dstbase + (uint32_t)(row * 272 + ch * 16)),
                        "l"((const void*)(&g_cB[srcrow + row][ch * 8])) : "memory");
    }
}

__global__ void __launch_bounds__(256, 2) kgemm()
{
    extern __shared__ __align__(16) unsigned char sm[];
    const uint32_t smem_base = (uint32_t)__cvta_generic_to_shared(sm);
    const int* sPk = (const int*)(sm + SMPK);
    float*      sZ = (float*)(sm + SMZ);

    const int tid  = threadIdx.x;
    const int lane = tid & 31;
    const int wid  = tid >> 5;
    const int wm   = wid >> 1;          // 0..3 : rows wm*16 .. +15
    const int wn   = wid & 1;           // 0..1 : cols wn*64 .. +63
    const int rowbase = blockIdx.x * 64;
    const int colbase = blockIdx.y * COLQ;

    // --- prologue: stage pk table + A tile (64 rows) into buf0 ---
    for (int i = tid; i < COLQ; i += 256)
        ((int*)(sm + SMPK))[i] = g_pk[colbase + i];
    for (int idx = tid; idx < 64 * 16; idx += 256) {
        int r = idx >> 4, ch = idx & 15;
        *(uint4*)(sm + SMB0 + r * 272 + ch * 16) =
            *(const uint4*)((const char*)g_cB[ROW0 + rowbase + r] + ch * 16);
    }
    __syncthreads();

    uint32_t afr[8][4];
    {
        uint32_t addr0 = smem_base + SMB0 + (wm * 16 + (lane & 15)) * 272 + ((lane >> 4) << 4);
#pragma unroll
        for (int ks = 0; ks < 8; ks++) {
            asm volatile("ldmatrix.sync.aligned.m8n8.x4.shared.b16 {%0,%1,%2,%3}, [%4];"
                         : "=r"(afr[ks][0]), "=r"(afr[ks][1]), "=r"(afr[ks][2]), "=r"(afr[ks][3])
                         : "r"(addr0 + ks * 32));
        }
    }
    __syncthreads();   // afr in regs; buf0 free for B tile 0

    // prime the ring: tile 0 -> buf0, tile 1 -> buf1 (two cp.async groups)
    cp_tile(smem_base + SMB0, colbase, tid);
    asm volatile("cp.async.commit_group;\n" ::: "memory");
    cp_tile(smem_base + SMB1, colbase + 128, tid);
    asm volatile("cp.async.commit_group;\n" ::: "memory");

    const int w0 = rowbase + wm * 16 + (lane >> 2);
    const int w1 = w0 + 8;
    const int rl0 = g_lab[ROW0 + w0];
    const int rl1 = g_lab[ROW0 + w1];
    float z0 = 0.f, z1 = 0.f;

    const int bj = lane >> 3;
    const int bn_off = ((bj & 2) << 2) + (lane & 7);
    const uint32_t bk_off = (uint32_t)((bj & 1) << 4);
    const uint32_t bufOf[3] = { SMB0, SMB1, SMB2 };

    for (int t = 0; t < NTILE; t++) {
        // tile t arrived?  (allow 1 outstanding group = tile t+1)
        if (t + 1 < NTILE)
            asm volatile("cp.async.wait_group 1;\n" ::: "memory");
        else
            asm volatile("cp.async.wait_group 0;\n" ::: "memory");
        __syncthreads();   // tile t visible to all; buf[(t+2)%3] readers done

        // issue tile t+2 into buf[(t+2)%3] (== buf[(t-1)%3], freed above)
        if (t + 2 < NTILE) {
            cp_tile(smem_base + bufOf[(t + 2) % 3], colbase + (t + 2) * 128, tid);
            asm volatile("cp.async.commit_group;\n" ::: "memory");
        }

        // MMA: 16(M) x 64(N) per warp, K=128, reading buf[t%3]
        const uint32_t bbase = smem_base + bufOf[t % 3];
        float acc[8][4] = {};
#pragma unroll
        for (int ks = 0; ks < 8; ks++) {
#pragma unroll
            for (int gix = 0; gix < 4; gix++) {
                uint32_t ba = bbase + (uint32_t)((wn * 64 + gix * 16 + bn_off) * 272)
                              + (uint32_t)(ks * 32) + bk_off;
                uint32_t b0, b1, b2, b3;
                asm volatile("ldmatrix.sync.aligned.m8n8.x4.shared.b16 {%0,%1,%2,%3}, [%4];"
                             : "=r"(b0), "=r"(b1), "=r"(b2), "=r"(b3) : "r"(ba));
                mma16816(acc[2 * gix],     afr[ks], b0, b1);
                mma16816(acc[2 * gix + 1], afr[ks], b2, b3);
            }
        }

        // epilogue: masked sum-of-exp + positive scatter (row-major)
        const int cb = t * 128 + wn * 64 + 2 * (lane & 3);
#pragma unroll
        for (int f = 0; f < 8; f++) {
            int2 pk = *(const int2*)&sPk[cb + f * 8];
            int l0 = pk.x & 0xffff, l1 = pk.y & 0xffff;
            float x00 = acc[f][0] * INV_T, x01 = acc[f][1] * INV_T;
            float x10 = acc[f][2] * INV_T, x11 = acc[f][3] * INV_T;
            bool e00 = (l0 == rl0), e01 = (l1 == rl0);
            bool e10 = (l0 == rl1), e11 = (l1 == rl1);
            z0 += __expf(e00 ? -2e30f : x00) + __expf(e01 ? -2e30f : x01);
            z1 += __expf(e10 ? -2e30f : x10) + __expf(e11 ? -2e30f : x11);
            if (e00) g_posD[w0 * MAXP + (pk.x >> 16)] = x00;
            if (e01) g_posD[w0 * MAXP + (pk.y >> 16)] = x01;
            if (e10) g_posD[w1 * MAXP + (pk.x >> 16)] = x10;
            if (e11) g_posD[w1 * MAXP + (pk.y >> 16)] = x11;
        }
        // (next iteration's top sync closes the read window on buf[t%3])
    }

    // reduce z across the 4 lanes sharing each row, combine the 2 col-halves
    z0 += __shfl_xor_sync(0xffffffffu, z0, 1);
    z0 += __shfl_xor_sync(0xffffffffu, z0, 2);
    z1 += __shfl_xor_sync(0xffffffffu, z1, 1);
    z1 += __shfl_xor_sync(0xffffffffu, z1, 2);
    if ((lane & 3) == 0) {
        int rloc = wm * 16 + (lane >> 2);
        sZ[wn * 64 + rloc]     = z0;
        sZ[wn * 64 + rloc + 8] = z1;
    }
    __syncthreads();
    if (tid < 64)
        g_rowZ[rowbase + tid][blockIdx.y] = sZ[tid] + sZ[64 + tid];
}

// ---------------------------------------------------------------------------
// Kernel R: warp per row (136 blocks x 1024 thr), coalesced posD reads,
// fused final mean + counter reset for graph replay.
// ---------------------------------------------------------------------------
__global__ void __launch_bounds__(1024) krow(float* __restrict__ out)
{
    __shared__ float sW[32];
    __shared__ bool amLast;

    int tid = threadIdx.x, lane = tid & 31, wid = tid >> 5;
    int w = blockIdx.x * 32 + wid;
    int g = ROW0 + w;
    int rl = g_lab[g];
    bool exc = (g < Bn) || (g == 8192);
    int cnt = g_cnt[rl];
    int selfRank = g_pk[g] >> 16;

    float4 zz = *(const float4*)g_rowZ[w];
    float lse = __logf((zz.x + zz.y) + (zz.z + zz.w));

    float s = 0.f;
    for (int idx = lane; idx < cnt; idx += 32) {
        float x = g_posD[w * MAXP + idx];      // coalesced 128B per warp
        if (!(exc && idx == selfRank)) s += fminf(0.f, x - lse);
    }
    s += __shfl_xor_sync(0xffffffffu, s, 16);
    s += __shfl_xor_sync(0xffffffffu, s, 8);
    s += __shfl_xor_sync(0xffffffffu, s, 4);
    s += __shfl_xor_sync(0xffffffffu, s, 2);
    s += __shfl_xor_sync(0xffffffffu, s, 1);
    if (lane == 0) sW[wid] = s / (float)(cnt - (exc ? 1 : 0));
    __syncthreads();

    if (wid == 0) {
        float v = sW[lane];
        v += __shfl_xor_sync(0xffffffffu, v, 16);
        v += __shfl_xor_sync(0xffffffffu, v, 8);
        v += __shfl_xor_sync(0xffffffffu, v, 4);
        v += __shfl_xor_sync(0xffffffffu, v, 2);
        v += __shfl_xor_sync(0xffffffffu, v, 1);
        if (lane == 0) {
            g_blkSum[blockIdx.x] = v;
            __threadfence();
            amLast = (atomicAdd(&g_ctr, 1u) == gridDim.x - 1);
        }
    }
    __syncthreads();
    if (amLast) {
        // reset class counters for the next graph replay
        if (tid < NCLS) g_cnt[tid] = 0;
        if (tid == 0) {
            float a = 0.f;
#pragma unroll
            for (int i = 0; i < KRB; i++) a += g_blkSum[i];
            float loss = -(a / (float)NR);
            out[0] = loss; out[1] = loss; out[2] = loss;
            g_ctr = 0u;
        }
    }
}

// ---------------------------------------------------------------------------
extern "C" void kernel_launch(void* const* d_in, const int* in_sizes, int n_in,
                              void* d_out, int out_size)
{
    const float* feat  = (const float*)d_in[0];
    const int*   label = (const int*)d_in[1];
    const float* fq    = (const float*)d_in[2];
    const float* fq2   = (const float*)d_in[3];
    const int*   lq    = (const int*)d_in[4];
    float* out = (float*)d_out;

    cudaFuncSetAttribute(kgemm, cudaFuncAttributeMaxDynamicSharedMemorySize, SMEM_BYTES);

    kprep<<<(N2 * 32) / 256, 256>>>(feat, label, fq, fq2, lq);
    kgemm<<<dim3(NR / 64, NQ), 256, SMEM_BYTES>>>();
    krow<<<KRB, 1024>>>(out);
}